// round 14
// baseline (speedup 1.0000x reference)
#include <cuda_runtime.h>
#include <cuda_fp16.h>
#include <cstdint>

#define NN 256
#define CH 20

// E/bias matrix, fp16, 2-pass split layout: 144 rows x 64 cols:
//   B cols 0..25  = hi(E[k]) (col25 = hi(bias))     -- pass 1: ah*bh
//   B cols 26..51 = hi(E[k-26]) (col51 = lo(bias))  -- pass 2: al*bh (+1.0*bias_lo)
//   B cols 52..63 = 0 ;  row n = (j*9+k9)*4 + i  where p = i*4+j
__device__ __align__(16) __half gEH[144 * 64];

__device__ __forceinline__ void mma16816(float& d0, float& d1, float& d2, float& d3,
                                         uint32_t a0, uint32_t a1, uint32_t a2, uint32_t a3,
                                         uint32_t b0, uint32_t b1) {
    asm volatile(
        "mma.sync.aligned.m16n8k16.row.col.f32.f16.f16.f32 "
        "{%0,%1,%2,%3}, {%4,%5,%6,%7}, {%8,%9}, {%0,%1,%2,%3};"
        : "+f"(d0), "+f"(d1), "+f"(d2), "+f"(d3)
        : "r"(a0), "r"(a1), "r"(a2), "r"(a3), "r"(b0), "r"(b1));
}

__device__ __forceinline__ void ldmx4(uint32_t& r0, uint32_t& r1, uint32_t& r2,
                                      uint32_t& r3, uint32_t a) {
    asm volatile("ldmatrix.sync.aligned.m8n8.x4.shared.b16 {%0,%1,%2,%3}, [%4];"
                 : "=r"(r0), "=r"(r1), "=r"(r2), "=r"(r3) : "r"(a));
}

// ---------------------------------------------------------------------------
// Kernel 1: compose W1/W2 -> 5x5 E + bias, fp16 2-pass layout.
// ---------------------------------------------------------------------------
__global__ void k_precompute(const float* __restrict__ W1, const float* __restrict__ b1,
                             const float* __restrict__ W2, const float* __restrict__ b2) {
    int w = blockIdx.x * 4 + (threadIdx.x >> 5);
    int lane = threadIdx.x & 31;
    if (w >= 144) return;
    int p = w / 9, k9 = w % 9;

    float e[25];
#pragma unroll
    for (int i = 0; i < 25; i++) e[i] = 0.f;
    float bacc = 0.f;

    if (lane < CH) {
        int c = lane;
        float w1[9];
        const float* w1p = W1 + (p * CH + c) * 9;
#pragma unroll
        for (int a = 0; a < 9; a++) w1[a] = __ldg(w1p + a);
        const float* w2p = W2 + ((p * 9 + k9) * CH + c) * 9;
        float s2 = 0.f;
#pragma unroll
        for (int bq = 0; bq < 9; bq++) {
            float w2v = __ldg(w2p + bq);
            s2 += w2v;
            int by = bq / 3, bx = bq % 3;
#pragma unroll
            for (int a = 0; a < 9; a++) {
                int ay = a / 3, ax = a % 3;
                e[(ay + by) * 5 + (ax + bx)] += w1[a] * w2v;
            }
        }
        bacc = s2 * __ldg(b1 + p * CH + c);
    }
#pragma unroll
    for (int o = 16; o > 0; o >>= 1) {
#pragma unroll
        for (int i = 0; i < 25; i++) e[i] += __shfl_xor_sync(0xFFFFFFFFu, e[i], o);
        bacc += __shfl_xor_sync(0xFFFFFFFFu, bacc, o);
    }

    if (lane == 0) {
        int i = p >> 2, j = p & 3;
        int n = (j * 9 + k9) * 4 + i;
        __half* d = gEH + n * 64;
        float B = __ldg(b2 + w) + bacc;
        __half bh = __float2half(B);
        __half bl = __float2half(B - __half2float(bh));
#pragma unroll
        for (int q = 0; q < 64; q++) {
            __half v;
            if (q < 26)      v = (q == 25) ? bh : __float2half(e[q]);
            else if (q < 52) v = (q == 51) ? bl : __float2half(e[q - 26]);
            else             v = __ushort_as_half(0);
            d[q] = v;
        }
    }
}

__device__ __forceinline__ constexpr int OFFJK2(int jk) {
    return (jk / 9) * 324 + ((jk % 9) / 3) * 18 + ((jk % 9) % 3);
}

// ---------------------------------------------------------------------------
// Kernel 2: HMMA K-GEMM (K'=64, fp16 split-2) + fused contraction.
// CTA = 16x16 pixels, warp = 2 pixel rows. Writes ALL pixels (composed value);
// k_border subtracts the out-of-bounds correction on the ring afterwards.
// ---------------------------------------------------------------------------
__global__ void __launch_bounds__(256, 4) k_main(const float* __restrict__ img,
                                                 const float* __restrict__ x,
                                                 float* __restrict__ y) {
    __shared__ uint32_t sImgP[400];                   // 20x20 packed (hi|lo<<16) fp16
    __shared__ float sX[1296];                        // 4 x 18 x 18
    __shared__ __align__(16) uint32_t sB[144 * 36];   // row stride 36 words (144 B)

    const int t = threadIdx.x;
    const int w = t >> 5, lane = t & 31;
    const int g = lane >> 2, tg = lane & 3;
    const int b = blockIdx.z, TR = blockIdx.y * 16, TC = blockIdx.x * 16;

    const float* imgb = img + b * NN * NN;
    for (int i = t; i < 400; i += 256) {
        int rr = i / 20, cc = i % 20;
        int gn = TR + rr - 2, gm = TC + cc - 2;
        float f = 0.f;
        if ((unsigned)gn < NN && (unsigned)gm < NN) f = __ldg(imgb + gn * NN + gm);
        __half h = __float2half(f);
        __half l = __float2half(f - __half2float(h));
        sImgP[i] = (uint32_t)__half_as_ushort(h)
                 | ((uint32_t)__half_as_ushort(l) << 16);
    }
#pragma unroll
    for (int j = 0; j < 4; j++) {
        const float* xb = x + (b * 4 + j) * NN * NN;
        for (int i = t; i < 324; i += 256) {
            int rr = i / 18, cc = i % 18;
            int gn = TR + rr - 1, gm = TC + cc - 1;
            float v = 0.f;
            if ((unsigned)gn < NN && (unsigned)gm < NN) v = __ldg(xb + gn * NN + gm);
            sX[j * 324 + i] = v;
        }
    }
    {   // stage B (144 x 64 fp16 = 1152 uint4), row stride 36 words
        const uint4* src = reinterpret_cast<const uint4*>(gEH);
        for (int i = t; i < 1152; i += 256) {
            int n = i >> 3, q = i & 7;
            uint4 v = __ldg(src + i);
            *reinterpret_cast<uint4*>(&sB[n * 36 + q * 4]) = v;
        }
    }
    __syncthreads();

    // --- build A fragments for two pixel rows (r0, r0+1): 4 K-steps ---
    const int r0 = 2 * w;
    const int pc0 = g, pc1 = g + 8;
    uint32_t af0[4][4], af1[4][4];
#pragma unroll
    for (int ks = 0; ks < 4; ks++) {
#pragma unroll
        for (int hf = 0; hf < 2; hf++) {
            const int c = ks * 16 + 2 * tg + 8 * hf;
            uint32_t v[2][4];
#pragma unroll
            for (int dc = 0; dc < 2; dc++) {
                const int cc = c + dc;
                int k, sh;
                if (cc < 26)      { k = cc;      sh = 0;  }
                else if (cc < 52) { k = cc - 26; sh = 16; }
                else              { k = 0;       sh = 0;  }
                const bool zero = (cc >= 52);
                const bool bias = (k == 25);
                const int o = (k / 5) * 20 + (k % 5);
                const int base = r0 * 20 + o;
                uint32_t u0, u1, u2, u3;
                if (zero)      { u0 = u1 = u2 = u3 = 0u; }
                else if (bias) { u0 = u1 = u2 = u3 = 0x3C00u; }  // fp16 1.0 both passes
                else {
                    u0 = (sImgP[base + pc0] >> sh) & 0xFFFFu;
                    u1 = (sImgP[base + pc1] >> sh) & 0xFFFFu;
                    u2 = (sImgP[base + 20 + pc0] >> sh) & 0xFFFFu;
                    u3 = (sImgP[base + 20 + pc1] >> sh) & 0xFFFFu;
                }
                v[dc][0] = u0; v[dc][1] = u1; v[dc][2] = u2; v[dc][3] = u3;
            }
            af0[ks][hf * 2 + 0] = v[0][0] | (v[1][0] << 16);
            af0[ks][hf * 2 + 1] = v[0][1] | (v[1][1] << 16);
            af1[ks][hf * 2 + 0] = v[0][2] | (v[1][2] << 16);
            af1[ks][hf * 2 + 1] = v[0][3] | (v[1][3] << 16);
        }
    }

    float sa00 = 0.f, sb00 = 0.f, sa01 = 0.f, sb01 = 0.f;
    float sa10 = 0.f, sb10 = 0.f, sa11 = 0.f, sb11 = 0.f;
    const int th = tg >> 1;
    const int xb0 = r0 * 18, xb1 = (r0 + 1) * 18;

    const uint32_t sbB = (uint32_t)__cvta_generic_to_shared(sB);
    const uint32_t mbase = sbB + (uint32_t)(lane & 7) * 144u + (uint32_t)(lane >> 3) * 16u;

#pragma unroll
    for (int ni = 0; ni < 18; ni++) {
        const uint32_t ad = mbase + (uint32_t)ni * 1152u;   // 8 rows * 144 B
        uint32_t c0, c1, c2, c3, c4, c5, c6, c7;
        ldmx4(c0, c1, c2, c3, ad);          // ks0, ks1
        ldmx4(c4, c5, c6, c7, ad + 64);     // ks2, ks3

        float d00 = 0.f, d01 = 0.f, d02 = 0.f, d03 = 0.f;
        float d10 = 0.f, d11 = 0.f, d12 = 0.f, d13 = 0.f;
        mma16816(d00, d01, d02, d03, af0[0][0], af0[0][1], af0[0][2], af0[0][3], c0, c1);
        mma16816(d10, d11, d12, d13, af1[0][0], af1[0][1], af1[0][2], af1[0][3], c0, c1);
        mma16816(d00, d01, d02, d03, af0[1][0], af0[1][1], af0[1][2], af0[1][3], c2, c3);
        mma16816(d10, d11, d12, d13, af1[1][0], af1[1][1], af1[1][2], af1[1][3], c2, c3);
        mma16816(d00, d01, d02, d03, af0[2][0], af0[2][1], af0[2][2], af0[2][3], c4, c5);
        mma16816(d10, d11, d12, d13, af1[2][0], af1[2][1], af1[2][2], af1[2][3], c4, c5);
        mma16816(d00, d01, d02, d03, af0[3][0], af0[3][1], af0[3][2], af0[3][3], c6, c7);
        mma16816(d10, d11, d12, d13, af1[3][0], af1[3][1], af1[3][2], af1[3][3], c6, c7);

        const int offA = OFFJK2(2 * ni);
        const int offB = OFFJK2(2 * ni + 1);
        const int off = th ? offB : offA;
        float x00 = sX[off + xb0 + pc0];
        float x01 = sX[off + xb0 + pc1];
        float x10 = sX[off + xb1 + pc0];
        float x11 = sX[off + xb1 + pc1];
        sa00 = fmaf(d00, x00, sa00);
        sb00 = fmaf(d01, x00, sb00);
        sa01 = fmaf(d02, x01, sa01);
        sb01 = fmaf(d03, x01, sb01);
        sa10 = fmaf(d10, x10, sa10);
        sb10 = fmaf(d11, x10, sb10);
        sa11 = fmaf(d12, x11, sa11);
        sb11 = fmaf(d13, x11, sb11);
    }

    sa00 += __shfl_xor_sync(0xFFFFFFFFu, sa00, 2);
    sb00 += __shfl_xor_sync(0xFFFFFFFFu, sb00, 2);
    sa01 += __shfl_xor_sync(0xFFFFFFFFu, sa01, 2);
    sb01 += __shfl_xor_sync(0xFFFFFFFFu, sb01, 2);
    sa10 += __shfl_xor_sync(0xFFFFFFFFu, sa10, 2);
    sb10 += __shfl_xor_sync(0xFFFFFFFFu, sb10, 2);
    sa11 += __shfl_xor_sync(0xFFFFFFFFu, sa11, 2);
    sb11 += __shfl_xor_sync(0xFFFFFFFFu, sb11, 2);

    if (tg < 2) {
        const int ch0 = tg * 2;
        const int gc0 = TC + pc0, gc1 = TC + pc1;
        const int gr0 = TR + r0;
        float* y0 = y + ((b * 4 + ch0) * NN + gr0) * NN;
        float* y1 = y + ((b * 4 + ch0 + 1) * NN + gr0) * NN;
        y0[gc0] = sa00; y1[gc0] = sb00;
        y0[gc1] = sa01; y1[gc1] = sb01;
        y0[NN + gc0] = sa10; y1[NN + gc0] = sb10;
        y0[NN + gc1] = sa11; y1[NN + gc1] = sb11;
    }
}

// ---------------------------------------------------------------------------
// Kernel 3: border CORRECTION (after k_main):
// exact = composed - sum_{q oob} W2[k,c,q] * htilde_c(pos_q).
// ---------------------------------------------------------------------------
__global__ void __launch_bounds__(256) k_border(const float* __restrict__ img,
                                                const float* __restrict__ x,
                                                const float* __restrict__ W1,
                                                const float* __restrict__ b1,
                                                const float* __restrict__ W2,
                                                float* __restrict__ y) {
    __shared__ __align__(16) float sW1p[20 * 12];
    __shared__ __align__(16) float sW2q[180 * 12];   // [q][c][k], k padded to 12
    __shared__ float sb1v[20];

    const int p = blockIdx.x;
    const int t = threadIdx.x;
    for (int i = t; i < 240; i += 256) {
        int row = i / 12, q = i % 12;
        sW1p[i] = (q < 9) ? W1[p * 180 + row * 9 + q] : 0.f;
    }
    for (int i = t; i < 2160; i += 256) {
        int qc = i / 12, kk = i % 12;
        int q = qc / 20, c = qc % 20;
        sW2q[i] = (kk < 9) ? W2[p * 1620 + kk * 180 + c * 9 + q] : 0.f;
    }
    if (t < 20) sb1v[t] = b1[p * 20 + t];
    __syncthreads();

    int idx = blockIdx.y * 256 + t;
    const bool active = (idx < 4080);
    int b = 0, n = 128, m = 128;
    if (active) {
        b = idx / 1020;
        int r = idx % 1020;
        if (r < 256)       { n = 0;   m = r; }
        else if (r < 512)  { n = 255; m = r - 256; }
        else if (r < 766)  { n = r - 511; m = 0;   }
        else               { n = r - 765; m = 255; }
    }

    const float* imgb = img + b * NN * NN;
    float ipat[25];
#pragma unroll
    for (int u = 0; u < 5; u++)
#pragma unroll
        for (int v = 0; v < 5; v++) {
            int gn = n + u - 2, gm = m + v - 2;
            ipat[u * 5 + v] = ((unsigned)gn < NN && (unsigned)gm < NN)
                              ? __ldg(imgb + gn * NN + gm) : 0.f;
        }

    float corr[9];
#pragma unroll
    for (int k = 0; k < 9; k++) corr[k] = 0.f;

#pragma unroll
    for (int qq = 0; qq < 9; qq++) {
        const int qy = qq / 3, qx = qq % 3;
        const int py = n + qy - 1, px = m + qx - 1;
        const bool oob = ((unsigned)py >= NN) | ((unsigned)px >= NN);
        if (__any_sync(0xFFFFFFFFu, oob)) {
            const float f = oob ? 1.f : 0.f;
#pragma unroll 1
            for (int c = 0; c < CH; c++) {
                const float4* w1v = reinterpret_cast<const float4*>(sW1p + c * 12);
                float4 wa = w1v[0], wb = w1v[1], wc = w1v[2];
                float h = sb1v[c];
                h = fmaf(wa.x, ipat[(qy + 0) * 5 + qx + 0], h);
                h = fmaf(wa.y, ipat[(qy + 0) * 5 + qx + 1], h);
                h = fmaf(wa.z, ipat[(qy + 0) * 5 + qx + 2], h);
                h = fmaf(wa.w, ipat[(qy + 1) * 5 + qx + 0], h);
                h = fmaf(wb.x, ipat[(qy + 1) * 5 + qx + 1], h);
                h = fmaf(wb.y, ipat[(qy + 1) * 5 + qx + 2], h);
                h = fmaf(wb.z, ipat[(qy + 2) * 5 + qx + 0], h);
                h = fmaf(wb.w, ipat[(qy + 2) * 5 + qx + 1], h);
                h = fmaf(wc.x, ipat[(qy + 2) * 5 + qx + 2], h);
                h *= f;
                const float4* w2v = reinterpret_cast<const float4*>(sW2q + (qq * 20 + c) * 12);
                float4 va = w2v[0], vb = w2v[1], vc = w2v[2];
                corr[0] = fmaf(va.x, h, corr[0]);
                corr[1] = fmaf(va.y, h, corr[1]);
                corr[2] = fmaf(va.z, h, corr[2]);
                corr[3] = fmaf(va.w, h, corr[3]);
                corr[4] = fmaf(vb.x, h, corr[4]);
                corr[5] = fmaf(vb.y, h, corr[5]);
                corr[6] = fmaf(vb.z, h, corr[6]);
                corr[7] = fmaf(vb.w, h, corr[7]);
                corr[8] = fmaf(vc.x, h, corr[8]);
            }
        }
    }

    const int i = p >> 2, j = p & 3;
    const float* xb = x + (b * 4 + j) * NN * NN;
    float s = 0.f;
#pragma unroll
    for (int k = 0; k < 9; k++) {
        int di = k / 3, dj = k % 3;
        int gn = n + di - 1, gm = m + dj - 1;
        float xv = ((unsigned)gn < NN && (unsigned)gm < NN)
                   ? __ldg(xb + gn * NN + gm) : 0.f;
        s += corr[k] * xv;
    }
    if (active) atomicAdd(&y[((b * 4 + i) * NN + n) * NN + m], -s);
}

// ---------------------------------------------------------------------------
extern "C" void kernel_launch(void* const* d_in, const int* in_sizes, int n_in,
                              void* d_out, int out_size) {
    const float* image = (const float*)d_in[0];
    const float* x     = (const float*)d_in[1];
    const float* W1    = (const float*)d_in[2];
    const float* b1    = (const float*)d_in[3];
    const float* W2    = (const float*)d_in[4];
    const float* b2    = (const float*)d_in[5];
    float* y = (float*)d_out;

    k_precompute<<<36, 128>>>(W1, b1, W2, b2);           // launch 1
    dim3 g2(16, 16, 4);                                  // 1024 CTAs
    k_main<<<g2, 256>>>(image, x, y);                    // launch 2
    dim3 g3(16, 16);
    k_border<<<g3, 256>>>(image, x, W1, b1, W2, y);      // launch 3
}